// round 14
// baseline (speedup 1.0000x reference)
#include <cuda_runtime.h>
#include <cuda_fp16.h>
#include <cstdint>
#include <math.h>

// ---------------- problem constants ----------------
#define B_ROWS 65536
#define D_IN   512
#define D_H    512
#define D_OUT  128
#define N_EXP  16
#define TILE_M 128
#define MAXP   (B_ROWS + N_EXP * TILE_M)   // 67584
#define MT1    (MAXP / TILE_M)             // 528 (gemm2 tiles)
#define NT1    (B_ROWS / TILE_M)           // 512 (gemm1 tiles, unsorted)
#define NCHUNK 4
#define CH_T   (NT1 / NCHUNK)               // 128 tiles per chunk

// ---- smem geometry: both operands fp16, 4 stages, PAD_H=40 (80B rows) ----
#define PAD_H 40
#define ROWB  (PAD_H * 2)                   // 80 bytes per row
#define STG_B (128 * ROWB)                  // 10240 per operand tile
#define STAGE (2 * STG_B)                   // 20480 per stage
#define NST   4
#define DSMEM (NST * STAGE)                 // 81920 -> 2 CTAs/SM

// ---------------- device scratch ----------------
__device__ __half g_xh[(size_t)B_ROWS * D_IN];          // x fp16, ORIGINAL order
__device__ __half g_h[(size_t)B_ROWS * D_H];            // hidden acts, ORIGINAL order
__device__ __half g_w1t[(size_t)D_H * D_IN];            // W1^T [n][k], fp16
__device__ __half g_wet[(size_t)N_EXP * D_OUT * D_H];   // We^T [e][o][k], fp16
__device__ int   g_cnt[32];                             // [0:16] counts, [16:32] cursor
__device__ int   g_sorted[MAXP];

// ---------------- helpers ----------------
__device__ __forceinline__ uint32_t smem_u32(const void* p) {
    uint32_t a;
    asm("{ .reg .u64 t; cvta.to.shared.u64 t, %1; cvt.u32.u64 %0, t; }" : "=r"(a) : "l"(p));
    return a;
}
__device__ __forceinline__ void cp16(uint32_t dst, const void* src) {
    asm volatile("cp.async.cg.shared.global [%0], [%1], 16;" :: "r"(dst), "l"(src));
}
#define CP_COMMIT()  asm volatile("cp.async.commit_group;")
#define CP_WAIT_2()  asm volatile("cp.async.wait_group 2;")

__device__ __forceinline__ void mma16(float* c, const uint32_t* a, const uint32_t* b) {
    asm volatile(
        "mma.sync.aligned.m16n8k16.row.col.f32.f16.f16.f32 "
        "{%0,%1,%2,%3}, {%4,%5,%6,%7}, {%8,%9}, {%0,%1,%2,%3};"
        : "+f"(c[0]), "+f"(c[1]), "+f"(c[2]), "+f"(c[3])
        : "r"(a[0]), "r"(a[1]), "r"(a[2]), "r"(a[3]), "r"(b[0]), "r"(b[1]));
}
__device__ __forceinline__ void ldm_x4(uint32_t* r, uint32_t addr) {
    asm volatile("ldmatrix.sync.aligned.m8n8.x4.shared.b16 {%0,%1,%2,%3}, [%4];"
        : "=r"(r[0]), "=r"(r[1]), "=r"(r[2]), "=r"(r[3]) : "r"(addr));
}

// ---------------- routing ----------------
__global__ void r1_count(const int* __restrict__ num, const int* __restrict__ c) {
    __shared__ int h[N_EXP];
    int tid = threadIdx.x;
    if (tid < N_EXP) h[tid] = 0;
    __syncthreads();
    int i = blockIdx.x * blockDim.x + tid;
    if (i < B_ROWS) atomicAdd(&h[c[num[i]]], 1);
    __syncthreads();
    if (tid < N_EXP && h[tid]) atomicAdd(&g_cnt[tid], h[tid]);
}
__global__ void r3_scatter(const int* __restrict__ num, const int* __restrict__ c) {
    __shared__ int sstart[N_EXP];
    int tid = threadIdx.x;
    if (tid < N_EXP) {                     // inline 16-entry padded scan
        int s = 0;
        for (int e2 = 0; e2 < tid; e2++) s += (g_cnt[e2] + TILE_M - 1) & ~(TILE_M - 1);
        sstart[tid] = s;
    }
    __syncthreads();
    int i = blockIdx.x * blockDim.x + tid;
    if (i >= B_ROWS) return;
    int e = c[num[i]];
    unsigned lane = tid & 31;
    unsigned mask = __match_any_sync(0xffffffffu, e);
    int leader = __ffs(mask) - 1;
    int rank = __popc(mask & ((1u << lane) - 1u));
    int base = 0;
    if ((int)lane == leader) base = atomicAdd(&g_cnt[16 + e], __popc(mask));
    base = __shfl_sync(0xffffffffu, base, leader);
    g_sorted[sstart[e] + base + rank] = i;
}

// ---------------- x -> fp16, original order, row-chunked ----------------
__global__ __launch_bounds__(256) void cvt_x(const float* __restrict__ x, int row0) {
    size_t base = (size_t)row0 * D_IN;
    size_t i = base + ((size_t)blockIdx.x * 256 + threadIdx.x) * 8;
    float4 v0 = *(const float4*)(x + i);
    float4 v1 = *(const float4*)(x + i + 4);
    __half2 h[4];
    h[0] = __floats2half2_rn(v0.x, v0.y);
    h[1] = __floats2half2_rn(v0.z, v0.w);
    h[2] = __floats2half2_rn(v1.x, v1.y);
    h[3] = __floats2half2_rn(v1.z, v1.w);
    *(uint4*)(g_xh + i) = *(uint4*)h;
}

// ---------------- weight transposes (fp16) ----------------
__global__ void tr_w1(const float* __restrict__ W1) {
    __shared__ float t[32][33];
    int x0 = blockIdx.x * 32;   // n
    int y0 = blockIdx.y * 32;   // k
    for (int i = threadIdx.y; i < 32; i += 8)
        t[i][threadIdx.x] = W1[(size_t)(y0 + i) * D_H + x0 + threadIdx.x];
    __syncthreads();
    for (int i = threadIdx.y; i < 32; i += 8)
        g_w1t[(size_t)(x0 + i) * D_IN + y0 + threadIdx.x] = __float2half_rn(t[threadIdx.x][i]);
}
__global__ void tr_we(const float* __restrict__ We) {
    __shared__ float t[32][33];
    int e = blockIdx.z;
    int x0 = blockIdx.x * 32;   // o
    int y0 = blockIdx.y * 32;   // k
    const float* src = We + (size_t)e * D_H * D_OUT;
    for (int i = threadIdx.y; i < 32; i += 8)
        t[i][threadIdx.x] = src[(size_t)(y0 + i) * D_OUT + x0 + threadIdx.x];
    __syncthreads();
    __half* dst = g_wet + (size_t)e * D_OUT * D_H;
    for (int i = threadIdx.y; i < 32; i += 8)
        dst[(size_t)(x0 + i) * D_H + y0 + threadIdx.x] = __float2half_rn(t[threadIdx.x][i]);
}

// ---------------- GEMM1: h = relu(x @ W1 + b1), ORIGINAL order, no routing dep ----------------
__global__ __launch_bounds__(256, 2) void gemm1(const float* __restrict__ b1, int t0) {
    __shared__ float bias_s[128];
    extern __shared__ char dsm[];

    const int tid = threadIdx.x, lane = tid & 31, wid = tid >> 5;
    const int bn = blockIdx.x;
    const int p0 = (blockIdx.y + t0) * TILE_M;

    if (tid < 128) bias_s[tid] = b1[bn * 128 + tid];
    __syncthreads();

    const uint32_t sb = smem_u32(dsm);

    const __half* asrc[2];
    const __half* bsrc[2];
    uint32_t adst[2], bdst[2];
#pragma unroll
    for (int i = 0; i < 2; i++) {
        int id = tid + i * 256;
        int r = id >> 2, q = id & 3;
        asrc[i] = g_xh + (size_t)(p0 + r) * D_IN + q * 8;
        bsrc[i] = g_w1t + (size_t)(bn * 128 + r) * D_IN + q * 8;
        adst[i] = sb + (uint32_t)(r * ROWB + q * 16);
        bdst[i] = adst[i] + STG_B;
    }
#pragma unroll
    for (int s = 0; s < 3; s++) {
        uint32_t off = (uint32_t)(s * STAGE);
        int k = s * 32;
#pragma unroll
        for (int i = 0; i < 2; i++) {
            cp16(adst[i] + off, asrc[i] + k);
            cp16(bdst[i] + off, bsrc[i] + k);
        }
        CP_COMMIT();
    }

    float acc[4][4][4];
#pragma unroll
    for (int mt = 0; mt < 4; mt++)
#pragma unroll
        for (int nt = 0; nt < 4; nt++)
#pragma unroll
            for (int k = 0; k < 4; k++) acc[mt][nt][k] = 0.f;

    const int wm = wid >> 2, wn = wid & 3;
    const int g = lane >> 3, lrow = lane & 7;

    uint32_t aoff[4], boff[2];
#pragma unroll
    for (int mt = 0; mt < 4; mt++)
        aoff[mt] = (uint32_t)((wm * 64 + mt * 16 + (g & 1) * 8 + lrow) * ROWB + (g >> 1) * 16);
#pragma unroll
    for (int p = 0; p < 2; p++)
        boff[p] = (uint32_t)(STG_B + (wn * 32 + p * 16 + (g >> 1) * 8 + lrow) * ROWB + (g & 1) * 16);

    for (int s = 0; s < 16; s++) {
        CP_WAIT_2();
        __syncthreads();
        if (s + 3 < 16) {
            uint32_t off = (uint32_t)(((s + 3) & (NST - 1)) * STAGE);
            int k = (s + 3) * 32;
#pragma unroll
            for (int i = 0; i < 2; i++) {
                cp16(adst[i] + off, asrc[i] + k);
                cp16(bdst[i] + off, bsrc[i] + k);
            }
        }
        CP_COMMIT();

        const uint32_t sbase = sb + (uint32_t)((s & (NST - 1)) * STAGE);
#pragma unroll
        for (int ks = 0; ks < 2; ks++) {
            uint32_t a[4][4], b[2][4];
#pragma unroll
            for (int mt = 0; mt < 4; mt++) ldm_x4(a[mt], sbase + aoff[mt] + ks * 32);
            ldm_x4(b[0], sbase + boff[0] + ks * 32);
            ldm_x4(b[1], sbase + boff[1] + ks * 32);
#pragma unroll
            for (int mt = 0; mt < 4; mt++)
#pragma unroll
                for (int nt = 0; nt < 4; nt++)
                    mma16(acc[mt][nt], a[mt], &b[nt >> 1][(nt & 1) * 2]);
        }
    }

    // epilogue: bias + relu -> g_h fp16 (original order)
    const int lr = lane >> 2, lc = lane & 3;
#pragma unroll
    for (int mt = 0; mt < 4; mt++) {
        int m = wm * 64 + mt * 16 + lr;
#pragma unroll
        for (int nt = 0; nt < 4; nt++) {
            int n = wn * 32 + nt * 8 + lc * 2;
            float bi0 = bias_s[n], bi1 = bias_s[n + 1];
            __half2 v0 = __floats2half2_rn(fmaxf(acc[mt][nt][0] + bi0, 0.f),
                                           fmaxf(acc[mt][nt][1] + bi1, 0.f));
            __half2 v1 = __floats2half2_rn(fmaxf(acc[mt][nt][2] + bi0, 0.f),
                                           fmaxf(acc[mt][nt][3] + bi1, 0.f));
            *(__half2*)(g_h + (size_t)(p0 + m) * D_H + bn * 128 + n) = v0;
            *(__half2*)(g_h + (size_t)(p0 + m + 8) * D_H + bn * 128 + n) = v1;
        }
    }
}

// ---------------- GEMM2: out[orig] = sigmoid(h[sorted-gather] @ We[e]^T + be[e]) ----------------
__global__ __launch_bounds__(256, 2) void gemm2(const float* __restrict__ be,
                                                float* __restrict__ out) {
    __shared__ int   rows_s[128];
    __shared__ float bias_s[128];
    __shared__ int   sstart[N_EXP + 1];
    extern __shared__ char dsm[];

    const int tid = threadIdx.x, lane = tid & 31, wid = tid >> 5;

    if (tid <= N_EXP) {
        int s = 0;
        for (int e2 = 0; e2 < tid; e2++) s += (g_cnt[e2] + TILE_M - 1) & ~(TILE_M - 1);
        sstart[tid] = s;
    }
    __syncthreads();

    const int p0 = blockIdx.x * TILE_M;
    if (p0 >= sstart[N_EXP]) return;

    int e = 0;
    while (e < N_EXP - 1 && sstart[e + 1] <= p0) e++;
    const int valid_end = sstart[e] + g_cnt[e];

    if (tid < 128) {
        int r = g_sorted[p0 + tid];
        rows_s[tid] = min(max(r, 0), B_ROWS - 1);   // clamp padding entries
        bias_s[tid] = be[e * D_OUT + tid];
    }
    __syncthreads();

    const uint32_t sb = smem_u32(dsm);
    const __half* Bb = g_wet + (size_t)e * D_OUT * D_H;

    const __half* asrc[2];
    const __half* bsrc[2];
    uint32_t adst[2], bdst[2];
#pragma unroll
    for (int i = 0; i < 2; i++) {
        int id = tid + i * 256;
        int r = id >> 2, q = id & 3;
        asrc[i] = g_h + (size_t)rows_s[r] * D_H + q * 8;   // gather A rows by sort
        bsrc[i] = Bb + (size_t)r * D_H + q * 8;
        adst[i] = sb + (uint32_t)(r * ROWB + q * 16);
        bdst[i] = adst[i] + STG_B;
    }
#pragma unroll
    for (int s = 0; s < 3; s++) {
        uint32_t off = (uint32_t)(s * STAGE);
        int k = s * 32;
#pragma unroll
        for (int i = 0; i < 2; i++) {
            cp16(adst[i] + off, asrc[i] + k);
            cp16(bdst[i] + off, bsrc[i] + k);
        }
        CP_COMMIT();
    }

    float acc[4][4][4];
#pragma unroll
    for (int mt = 0; mt < 4; mt++)
#pragma unroll
        for (int nt = 0; nt < 4; nt++)
#pragma unroll
            for (int k = 0; k < 4; k++) acc[mt][nt][k] = 0.f;

    const int wm = wid >> 2, wn = wid & 3;
    const int g = lane >> 3, lrow = lane & 7;

    uint32_t aoff[4], boff[2];
#pragma unroll
    for (int mt = 0; mt < 4; mt++)
        aoff[mt] = (uint32_t)((wm * 64 + mt * 16 + (g & 1) * 8 + lrow) * ROWB + (g >> 1) * 16);
#pragma unroll
    for (int p = 0; p < 2; p++)
        boff[p] = (uint32_t)(STG_B + (wn * 32 + p * 16 + (g >> 1) * 8 + lrow) * ROWB + (g & 1) * 16);

    for (int s = 0; s < 16; s++) {
        CP_WAIT_2();
        __syncthreads();
        if (s + 3 < 16) {
            uint32_t off = (uint32_t)(((s + 3) & (NST - 1)) * STAGE);
            int k = (s + 3) * 32;
#pragma unroll
            for (int i = 0; i < 2; i++) {
                cp16(adst[i] + off, asrc[i] + k);
                cp16(bdst[i] + off, bsrc[i] + k);
            }
        }
        CP_COMMIT();

        const uint32_t sbase = sb + (uint32_t)((s & (NST - 1)) * STAGE);
#pragma unroll
        for (int ks = 0; ks < 2; ks++) {
            uint32_t a[4][4], b[2][4];
#pragma unroll
            for (int mt = 0; mt < 4; mt++) ldm_x4(a[mt], sbase + aoff[mt] + ks * 32);
            ldm_x4(b[0], sbase + boff[0] + ks * 32);
            ldm_x4(b[1], sbase + boff[1] + ks * 32);
#pragma unroll
            for (int mt = 0; mt < 4; mt++)
#pragma unroll
                for (int nt = 0; nt < 4; nt++)
                    mma16(acc[mt][nt], a[mt], &b[nt >> 1][(nt & 1) * 2]);
        }
    }

    // epilogue: bias + sigmoid, scatter valid rows
    const int lr = lane >> 2, lc = lane & 3;
#pragma unroll
    for (int mt = 0; mt < 4; mt++) {
        int m = wm * 64 + mt * 16 + lr;
#pragma unroll
        for (int nt = 0; nt < 4; nt++) {
            int n = wn * 32 + nt * 8 + lc * 2;
            float bi0 = bias_s[n], bi1 = bias_s[n + 1];
            if (p0 + m < valid_end) {
                float2 v;
                v.x = 1.f / (1.f + __expf(-(acc[mt][nt][0] + bi0)));
                v.y = 1.f / (1.f + __expf(-(acc[mt][nt][1] + bi1)));
                *(float2*)(out + (size_t)rows_s[m] * D_OUT + n) = v;
            }
            if (p0 + m + 8 < valid_end) {
                float2 v;
                v.x = 1.f / (1.f + __expf(-(acc[mt][nt][2] + bi0)));
                v.y = 1.f / (1.f + __expf(-(acc[mt][nt][3] + bi1)));
                *(float2*)(out + (size_t)rows_s[m + 8] * D_OUT + n) = v;
            }
        }
    }
}

// ---------------- launch: chunked cvt->gemm1 pipeline, 2-stream budget ----------------
extern "C" void kernel_launch(void* const* d_in, const int* in_sizes, int n_in,
                              void* d_out, int out_size) {
    const float* x   = (const float*)d_in[0];
    const int*   num = (const int*)d_in[1];
    const int*   c   = (const int*)d_in[2];
    const float* W1  = (const float*)d_in[3];
    const float* b1  = (const float*)d_in[4];
    const float* We  = (const float*)d_in[5];
    const float* be  = (const float*)d_in[6];
    float* out = (float*)d_out;

    static cudaStream_t sC = nullptr, sW = nullptr;
    static cudaEvent_t evFork, evCc[NCHUNK], evW1, evR;
    static void* cnt_ptr = nullptr;
    if (!sC) {
        cudaFuncSetAttribute(gemm1, cudaFuncAttributeMaxDynamicSharedMemorySize, DSMEM);
        cudaFuncSetAttribute(gemm2, cudaFuncAttributeMaxDynamicSharedMemorySize, DSMEM);
        cudaStreamCreateWithFlags(&sC, cudaStreamNonBlocking);
        cudaStreamCreateWithFlags(&sW, cudaStreamNonBlocking);
        cudaEventCreateWithFlags(&evFork, cudaEventDisableTiming);
        for (int i = 0; i < NCHUNK; i++) cudaEventCreateWithFlags(&evCc[i], cudaEventDisableTiming);
        cudaEventCreateWithFlags(&evW1, cudaEventDisableTiming);
        cudaEventCreateWithFlags(&evR,  cudaEventDisableTiming);
        cudaGetSymbolAddress(&cnt_ptr, g_cnt);
    }

    // fork
    cudaEventRecord(evFork, 0);
    cudaStreamWaitEvent(sC, evFork, 0);
    cudaStreamWaitEvent(sW, evFork, 0);

    // sC: x -> fp16 in 4 row-chunks (event after each)
    const int rows_per_chunk = B_ROWS / NCHUNK;               // 16384
    const int blocks_per_chunk = rows_per_chunk * D_IN / (256 * 8);
    for (int i = 0; i < NCHUNK; i++) {
        cvt_x<<<blocks_per_chunk, 256, 0, sC>>>(x, i * rows_per_chunk);
        cudaEventRecord(evCc[i], sC);
    }

    // sW: tr_w1 first (gemm1 dep), then tr_we + routing (gemm2-only deps)
    dim3 tb(32, 8);
    tr_w1<<<dim3(16, 16), tb, 0, sW>>>(W1);
    cudaEventRecord(evW1, sW);
    tr_we<<<dim3(4, 16, 16), tb, 0, sW>>>(We);
    cudaMemsetAsync(cnt_ptr, 0, 32 * sizeof(int), sW);
    r1_count<<<B_ROWS / 256, 256, 0, sW>>>(num, c);
    r3_scatter<<<B_ROWS / 256, 256, 0, sW>>>(num, c);
    cudaEventRecord(evR, sW);

    // main: gemm1 chunks pipelined behind cvt chunks (same stream, sequential work)
    cudaStreamWaitEvent(0, evW1, 0);
    for (int i = 0; i < NCHUNK; i++) {
        cudaStreamWaitEvent(0, evCc[i], 0);
        gemm1<<<dim3(4, CH_T), 256, DSMEM>>>(b1, i * CH_T);
    }

    // gemm2 after routing + all gemm1 chunks
    cudaStreamWaitEvent(0, evR, 0);
    gemm2<<<MT1, 256, DSMEM>>>(be, out);
}

// round 15
// speedup vs baseline: 1.0687x; 1.0687x over previous
#include <cuda_runtime.h>
#include <cuda_fp16.h>
#include <cstdint>
#include <math.h>

// ---------------- problem constants ----------------
#define B_ROWS 65536
#define D_IN   512
#define D_H    512
#define D_OUT  128
#define N_EXP  16
#define TILE_M 128
#define MAXP   (B_ROWS + N_EXP * TILE_M)   // 67584
#define MT1    (MAXP / TILE_M)             // 528
#define PGRID  304                          // 152 SMs x 2 CTAs (persistent grid)

// ---- smem geometry: both operands fp16, 4 stages, PAD_H=40 (80B rows) ----
#define PAD_H 40
#define ROWB  (PAD_H * 2)                   // 80 bytes per row
#define STG_B (128 * ROWB)                  // 10240 per operand tile
#define STAGE (2 * STG_B)                   // 20480 per stage
#define NST   4
#define DSMEM (NST * STAGE)                 // 81920 -> 2 CTAs/SM

// ---------------- device scratch ----------------
__device__ __half g_xh[(size_t)B_ROWS * D_IN];          // x fp16, ORIGINAL order
__device__ __half g_h[(size_t)MAXP * D_H];              // sorted hidden acts, fp16
__device__ __half g_w1t[(size_t)D_H * D_IN];            // W1^T [n][k], fp16
__device__ __half g_wet[(size_t)N_EXP * D_OUT * D_H];   // We^T [e][o][k], fp16
__device__ int   g_cnt[32];                             // [0:16] counts, [16:32] cursor
__device__ int   g_sorted[MAXP];

// ---------------- helpers ----------------
__device__ __forceinline__ uint32_t smem_u32(const void* p) {
    uint32_t a;
    asm("{ .reg .u64 t; cvta.to.shared.u64 t, %1; cvt.u32.u64 %0, t; }" : "=r"(a) : "l"(p));
    return a;
}
__device__ __forceinline__ void cp16(uint32_t dst, const void* src) {
    asm volatile("cp.async.cg.shared.global [%0], [%1], 16;" :: "r"(dst), "l"(src));
}
#define CP_COMMIT()  asm volatile("cp.async.commit_group;")
#define CP_WAIT_2()  asm volatile("cp.async.wait_group 2;")

__device__ __forceinline__ void mma16(float* c, const uint32_t* a, const uint32_t* b) {
    asm volatile(
        "mma.sync.aligned.m16n8k16.row.col.f32.f16.f16.f32 "
        "{%0,%1,%2,%3}, {%4,%5,%6,%7}, {%8,%9}, {%0,%1,%2,%3};"
        : "+f"(c[0]), "+f"(c[1]), "+f"(c[2]), "+f"(c[3])
        : "r"(a[0]), "r"(a[1]), "r"(a[2]), "r"(a[3]), "r"(b[0]), "r"(b[1]));
}
__device__ __forceinline__ void ldm_x4(uint32_t* r, uint32_t addr) {
    asm volatile("ldmatrix.sync.aligned.m8n8.x4.shared.b16 {%0,%1,%2,%3}, [%4];"
        : "=r"(r[0]), "=r"(r[1]), "=r"(r[2]), "=r"(r[3]) : "r"(addr));
}

// ---------------- routing ----------------
__global__ void r1_count(const int* __restrict__ num, const int* __restrict__ c) {
    __shared__ int h[N_EXP];
    int tid = threadIdx.x;
    if (tid < N_EXP) h[tid] = 0;
    __syncthreads();
    int i = blockIdx.x * blockDim.x + tid;
    if (i < B_ROWS) atomicAdd(&h[c[num[i]]], 1);
    __syncthreads();
    if (tid < N_EXP && h[tid]) atomicAdd(&g_cnt[tid], h[tid]);
}
__global__ void r3_scatter(const int* __restrict__ num, const int* __restrict__ c) {
    __shared__ int sstart[N_EXP];
    int tid = threadIdx.x;
    if (tid < N_EXP) {                     // inline 16-entry padded scan
        int s = 0;
        for (int e2 = 0; e2 < tid; e2++) s += (g_cnt[e2] + TILE_M - 1) & ~(TILE_M - 1);
        sstart[tid] = s;
    }
    __syncthreads();
    int i = blockIdx.x * blockDim.x + tid;
    if (i >= B_ROWS) return;
    int e = c[num[i]];
    unsigned lane = tid & 31;
    unsigned mask = __match_any_sync(0xffffffffu, e);
    int leader = __ffs(mask) - 1;
    int rank = __popc(mask & ((1u << lane) - 1u));
    int base = 0;
    if ((int)lane == leader) base = atomicAdd(&g_cnt[16 + e], __popc(mask));
    base = __shfl_sync(0xffffffffu, base, leader);
    g_sorted[sstart[e] + base + rank] = i;
}

// ---------------- x -> fp16, original order (pure streaming) ----------------
__global__ __launch_bounds__(256) void cvt_x(const float* __restrict__ x) {
    size_t i = ((size_t)blockIdx.x * 256 + threadIdx.x) * 8;
    float4 v0 = *(const float4*)(x + i);
    float4 v1 = *(const float4*)(x + i + 4);
    __half2 h[4];
    h[0] = __floats2half2_rn(v0.x, v0.y);
    h[1] = __floats2half2_rn(v0.z, v0.w);
    h[2] = __floats2half2_rn(v1.x, v1.y);
    h[3] = __floats2half2_rn(v1.z, v1.w);
    *(uint4*)(g_xh + i) = *(uint4*)h;
}

// ---------------- weight transposes (fp16) ----------------
__global__ void tr_w1(const float* __restrict__ W1) {
    __shared__ float t[32][33];
    int x0 = blockIdx.x * 32;   // n
    int y0 = blockIdx.y * 32;   // k
    for (int i = threadIdx.y; i < 32; i += 8)
        t[i][threadIdx.x] = W1[(size_t)(y0 + i) * D_H + x0 + threadIdx.x];
    __syncthreads();
    for (int i = threadIdx.y; i < 32; i += 8)
        g_w1t[(size_t)(x0 + i) * D_IN + y0 + threadIdx.x] = __float2half_rn(t[threadIdx.x][i]);
}
__global__ void tr_we(const float* __restrict__ We) {
    __shared__ float t[32][33];
    int e = blockIdx.z;
    int x0 = blockIdx.x * 32;   // o
    int y0 = blockIdx.y * 32;   // k
    const float* src = We + (size_t)e * D_H * D_OUT;
    for (int i = threadIdx.y; i < 32; i += 8)
        t[i][threadIdx.x] = src[(size_t)(y0 + i) * D_OUT + x0 + threadIdx.x];
    __syncthreads();
    __half* dst = g_wet + (size_t)e * D_OUT * D_H;
    for (int i = threadIdx.y; i < 32; i += 8)
        dst[(size_t)(x0 + i) * D_H + y0 + threadIdx.x] = __float2half_rn(t[threadIdx.x][i]);
}

// ---------------- GEMM1 (persistent): h = relu(x[sorted] @ W1 + b1) ----------------
__global__ __launch_bounds__(256, 2) void gemm1(const float* __restrict__ b1) {
    __shared__ int   rows_s[128];
    __shared__ float bias_s[128];
    __shared__ int   s_total;
    extern __shared__ char dsm[];

    const int tid = threadIdx.x, lane = tid & 31, wid = tid >> 5;

    if (tid == 0) {
        int s = 0;
        for (int e2 = 0; e2 < N_EXP; e2++) s += (g_cnt[e2] + TILE_M - 1) & ~(TILE_M - 1);
        s_total = s;
    }
    __syncthreads();
    const int total = s_total;

    const uint32_t sb = smem_u32(dsm);
    const int wm = wid >> 2, wn = wid & 3;
    const int g = lane >> 3, lrow = lane & 7;

    uint32_t aoff[4], boff[2];
#pragma unroll
    for (int mt = 0; mt < 4; mt++)
        aoff[mt] = (uint32_t)((wm * 64 + mt * 16 + (g & 1) * 8 + lrow) * ROWB + (g >> 1) * 16);
#pragma unroll
    for (int p = 0; p < 2; p++)
        boff[p] = (uint32_t)(STG_B + (wn * 32 + p * 16 + (g >> 1) * 8 + lrow) * ROWB + (g & 1) * 16);

    const int njobs = 4 * MT1;
    for (int job = blockIdx.x; job < njobs; job += gridDim.x) {
        const int t  = job >> 2;
        const int bn = job & 3;
        const int p0 = t * TILE_M;
        if (p0 >= total) continue;

        __syncthreads();                   // protect rows_s/bias_s overwrite
        if (tid < 128) {
            int r = g_sorted[p0 + tid];
            rows_s[tid] = min(max(r, 0), B_ROWS - 1);
            bias_s[tid] = b1[bn * 128 + tid];
        }
        __syncthreads();

        const __half* asrc[2];
        const __half* bsrc[2];
        uint32_t adst[2], bdst[2];
#pragma unroll
        for (int i = 0; i < 2; i++) {
            int id = tid + i * 256;
            int r = id >> 2, q = id & 3;
            asrc[i] = g_xh + (size_t)rows_s[r] * D_IN + q * 8;
            bsrc[i] = g_w1t + (size_t)(bn * 128 + r) * D_IN + q * 8;
            adst[i] = sb + (uint32_t)(r * ROWB + q * 16);
            bdst[i] = adst[i] + STG_B;
        }
#pragma unroll
        for (int s = 0; s < 3; s++) {
            uint32_t off = (uint32_t)(s * STAGE);
            int k = s * 32;
#pragma unroll
            for (int i = 0; i < 2; i++) {
                cp16(adst[i] + off, asrc[i] + k);
                cp16(bdst[i] + off, bsrc[i] + k);
            }
            CP_COMMIT();
        }

        float acc[4][4][4];
#pragma unroll
        for (int mt = 0; mt < 4; mt++)
#pragma unroll
            for (int nt = 0; nt < 4; nt++)
#pragma unroll
                for (int k = 0; k < 4; k++) acc[mt][nt][k] = 0.f;

        for (int s = 0; s < 16; s++) {
            CP_WAIT_2();
            __syncthreads();
            if (s + 3 < 16) {
                uint32_t off = (uint32_t)(((s + 3) & (NST - 1)) * STAGE);
                int k = (s + 3) * 32;
#pragma unroll
                for (int i = 0; i < 2; i++) {
                    cp16(adst[i] + off, asrc[i] + k);
                    cp16(bdst[i] + off, bsrc[i] + k);
                }
            }
            CP_COMMIT();

            const uint32_t sbase = sb + (uint32_t)((s & (NST - 1)) * STAGE);
#pragma unroll
            for (int ks = 0; ks < 2; ks++) {
                uint32_t a[4][4], b[2][4];
#pragma unroll
                for (int mt = 0; mt < 4; mt++) ldm_x4(a[mt], sbase + aoff[mt] + ks * 32);
                ldm_x4(b[0], sbase + boff[0] + ks * 32);
                ldm_x4(b[1], sbase + boff[1] + ks * 32);
#pragma unroll
                for (int mt = 0; mt < 4; mt++)
#pragma unroll
                    for (int nt = 0; nt < 4; nt++)
                        mma16(acc[mt][nt], a[mt], &b[nt >> 1][(nt & 1) * 2]);
            }
        }

        // epilogue: bias + relu -> g_h fp16 (sorted order)
        const int lr = lane >> 2, lc = lane & 3;
#pragma unroll
        for (int mt = 0; mt < 4; mt++) {
            int m = wm * 64 + mt * 16 + lr;
#pragma unroll
            for (int nt = 0; nt < 4; nt++) {
                int n = wn * 32 + nt * 8 + lc * 2;
                float bi0 = bias_s[n], bi1 = bias_s[n + 1];
                __half2 v0 = __floats2half2_rn(fmaxf(acc[mt][nt][0] + bi0, 0.f),
                                               fmaxf(acc[mt][nt][1] + bi1, 0.f));
                __half2 v1 = __floats2half2_rn(fmaxf(acc[mt][nt][2] + bi0, 0.f),
                                               fmaxf(acc[mt][nt][3] + bi1, 0.f));
                *(__half2*)(g_h + (size_t)(p0 + m) * D_H + bn * 128 + n) = v0;
                *(__half2*)(g_h + (size_t)(p0 + m + 8) * D_H + bn * 128 + n) = v1;
            }
        }
    }
}

// ---------------- GEMM2 (persistent): out[orig] = sigmoid(h @ We[e]^T + be[e]) ----------------
__global__ __launch_bounds__(256, 2) void gemm2(const float* __restrict__ be,
                                                float* __restrict__ out) {
    __shared__ int   rows_s[128];
    __shared__ float bias_s[128];
    __shared__ int   sstart[N_EXP + 1];
    extern __shared__ char dsm[];

    const int tid = threadIdx.x, lane = tid & 31, wid = tid >> 5;

    if (tid <= N_EXP) {
        int s = 0;
        for (int e2 = 0; e2 < tid; e2++) s += (g_cnt[e2] + TILE_M - 1) & ~(TILE_M - 1);
        sstart[tid] = s;
    }
    __syncthreads();

    const uint32_t sb = smem_u32(dsm);
    const int wm = wid >> 2, wn = wid & 3;
    const int g = lane >> 3, lrow = lane & 7;

    uint32_t aoff[4], boff[2];
#pragma unroll
    for (int mt = 0; mt < 4; mt++)
        aoff[mt] = (uint32_t)((wm * 64 + mt * 16 + (g & 1) * 8 + lrow) * ROWB + (g >> 1) * 16);
#pragma unroll
    for (int p = 0; p < 2; p++)
        boff[p] = (uint32_t)(STG_B + (wn * 32 + p * 16 + (g >> 1) * 8 + lrow) * ROWB + (g & 1) * 16);

    for (int t = blockIdx.x; t < MT1; t += gridDim.x) {
        const int p0 = t * TILE_M;
        if (p0 >= sstart[N_EXP]) continue;

        int e = 0;
        while (e < N_EXP - 1 && sstart[e + 1] <= p0) e++;
        const int valid_end = sstart[e] + g_cnt[e];

        __syncthreads();                   // protect rows_s/bias_s overwrite
        if (tid < 128) {
            rows_s[tid] = g_sorted[p0 + tid];
            bias_s[tid] = be[e * D_OUT + tid];
        }
        __syncthreads();

        const __half* Ab = g_h + (size_t)p0 * D_H;
        const __half* Bb = g_wet + (size_t)e * D_OUT * D_H;

        const __half* asrc[2];
        const __half* bsrc[2];
        uint32_t adst[2], bdst[2];
#pragma unroll
        for (int i = 0; i < 2; i++) {
            int id = tid + i * 256;
            int r = id >> 2, q = id & 3;
            asrc[i] = Ab + (size_t)r * D_H + q * 8;
            bsrc[i] = Bb + (size_t)r * D_H + q * 8;
            adst[i] = sb + (uint32_t)(r * ROWB + q * 16);
            bdst[i] = adst[i] + STG_B;
        }
#pragma unroll
        for (int s = 0; s < 3; s++) {
            uint32_t off = (uint32_t)(s * STAGE);
            int k = s * 32;
#pragma unroll
            for (int i = 0; i < 2; i++) {
                cp16(adst[i] + off, asrc[i] + k);
                cp16(bdst[i] + off, bsrc[i] + k);
            }
            CP_COMMIT();
        }

        float acc[4][4][4];
#pragma unroll
        for (int mt = 0; mt < 4; mt++)
#pragma unroll
            for (int nt = 0; nt < 4; nt++)
#pragma unroll
                for (int k = 0; k < 4; k++) acc[mt][nt][k] = 0.f;

        for (int s = 0; s < 16; s++) {
            CP_WAIT_2();
            __syncthreads();
            if (s + 3 < 16) {
                uint32_t off = (uint32_t)(((s + 3) & (NST - 1)) * STAGE);
                int k = (s + 3) * 32;
#pragma unroll
                for (int i = 0; i < 2; i++) {
                    cp16(adst[i] + off, asrc[i] + k);
                    cp16(bdst[i] + off, bsrc[i] + k);
                }
            }
            CP_COMMIT();

            const uint32_t sbase = sb + (uint32_t)((s & (NST - 1)) * STAGE);
#pragma unroll
            for (int ks = 0; ks < 2; ks++) {
                uint32_t a[4][4], b[2][4];
#pragma unroll
                for (int mt = 0; mt < 4; mt++) ldm_x4(a[mt], sbase + aoff[mt] + ks * 32);
                ldm_x4(b[0], sbase + boff[0] + ks * 32);
                ldm_x4(b[1], sbase + boff[1] + ks * 32);
#pragma unroll
                for (int mt = 0; mt < 4; mt++)
#pragma unroll
                    for (int nt = 0; nt < 4; nt++)
                        mma16(acc[mt][nt], a[mt], &b[nt >> 1][(nt & 1) * 2]);
            }
        }

        // epilogue: bias + sigmoid, scatter valid rows
        const int lr = lane >> 2, lc = lane & 3;
#pragma unroll
        for (int mt = 0; mt < 4; mt++) {
            int m = wm * 64 + mt * 16 + lr;
#pragma unroll
            for (int nt = 0; nt < 4; nt++) {
                int n = wn * 32 + nt * 8 + lc * 2;
                float bi0 = bias_s[n], bi1 = bias_s[n + 1];
                if (p0 + m < valid_end) {
                    float2 v;
                    v.x = 1.f / (1.f + __expf(-(acc[mt][nt][0] + bi0)));
                    v.y = 1.f / (1.f + __expf(-(acc[mt][nt][1] + bi1)));
                    *(float2*)(out + (size_t)rows_s[m] * D_OUT + n) = v;
                }
                if (p0 + m + 8 < valid_end) {
                    float2 v;
                    v.x = 1.f / (1.f + __expf(-(acc[mt][nt][2] + bi0)));
                    v.y = 1.f / (1.f + __expf(-(acc[mt][nt][3] + bi1)));
                    *(float2*)(out + (size_t)rows_s[m + 8] * D_OUT + n) = v;
                }
            }
        }
    }
}

// ---------------- launch (multi-stream fork/join, graph-capturable) ----------------
extern "C" void kernel_launch(void* const* d_in, const int* in_sizes, int n_in,
                              void* d_out, int out_size) {
    const float* x   = (const float*)d_in[0];
    const int*   num = (const int*)d_in[1];
    const int*   c   = (const int*)d_in[2];
    const float* W1  = (const float*)d_in[3];
    const float* b1  = (const float*)d_in[4];
    const float* We  = (const float*)d_in[5];
    const float* be  = (const float*)d_in[6];
    float* out = (float*)d_out;

    static cudaStream_t s1 = nullptr, s2 = nullptr;
    static cudaEvent_t evFork, evC, evW;
    static void* cnt_ptr = nullptr;
    if (!s1) {
        cudaFuncSetAttribute(gemm1, cudaFuncAttributeMaxDynamicSharedMemorySize, DSMEM);
        cudaFuncSetAttribute(gemm2, cudaFuncAttributeMaxDynamicSharedMemorySize, DSMEM);
        cudaStreamCreateWithFlags(&s1, cudaStreamNonBlocking);
        cudaStreamCreateWithFlags(&s2, cudaStreamNonBlocking);
        cudaEventCreateWithFlags(&evFork, cudaEventDisableTiming);
        cudaEventCreateWithFlags(&evC,    cudaEventDisableTiming);
        cudaEventCreateWithFlags(&evW,    cudaEventDisableTiming);
        cudaGetSymbolAddress(&cnt_ptr, g_cnt);
    }

    // fork from the (captured) default stream
    cudaEventRecord(evFork, 0);
    cudaStreamWaitEvent(s1, evFork, 0);
    cudaStreamWaitEvent(s2, evFork, 0);

    // s1: x -> fp16 (independent of routing)
    cvt_x<<<(B_ROWS * D_IN) / (256 * 8), 256, 0, s1>>>(x);
    cudaEventRecord(evC, s1);

    // s2: weight transposes
    dim3 tb(32, 8);
    tr_w1<<<dim3(16, 16), tb, 0, s2>>>(W1);
    tr_we<<<dim3(4, 16, 16), tb, 0, s2>>>(We);
    cudaEventRecord(evW, s2);

    // main: routing chain
    cudaMemsetAsync(cnt_ptr, 0, 32 * sizeof(int), 0);
    r1_count<<<B_ROWS / 256, 256>>>(num, c);
    r3_scatter<<<B_ROWS / 256, 256>>>(num, c);

    // join, then persistent GEMMs
    cudaStreamWaitEvent(0, evC, 0);
    cudaStreamWaitEvent(0, evW, 0);
    gemm1<<<PGRID, 256, DSMEM>>>(b1);
    gemm2<<<PGRID, 256, DSMEM>>>(be, out);
}

// round 16
// speedup vs baseline: 1.0838x; 1.0142x over previous
#include <cuda_runtime.h>
#include <cuda_fp16.h>
#include <cstdint>
#include <math.h>

// ---------------- problem constants ----------------
#define B_ROWS 65536
#define D_IN   512
#define D_H    512
#define D_OUT  128
#define N_EXP  16
#define TILE_M 128
#define MAXP   (B_ROWS + N_EXP * TILE_M)   // 67584
#define MT1    (MAXP / TILE_M)             // 528 (gemm2 tiles)
#define NT1    (B_ROWS / TILE_M)           // 512 (gemm1 tiles, unsorted)
#define NCHUNK 2
#define CH_T   (NT1 / NCHUNK)               // 256 tiles per chunk

// ---- smem geometry: both operands fp16, 4 stages, PAD_H=40 (80B rows) ----
#define PAD_H 40
#define ROWB  (PAD_H * 2)                   // 80 bytes per row
#define STG_B (128 * ROWB)                  // 10240 per operand tile
#define STAGE (2 * STG_B)                   // 20480 per stage
#define NST   4
#define DSMEM (NST * STAGE)                 // 81920 -> 2 CTAs/SM

// ---------------- device scratch ----------------
__device__ __half g_xh[(size_t)B_ROWS * D_IN];          // x fp16, ORIGINAL order
__device__ __half g_h[(size_t)B_ROWS * D_H];            // hidden acts, ORIGINAL order
__device__ __half g_w1t[(size_t)D_H * D_IN];            // W1^T [n][k], fp16
__device__ __half g_wet[(size_t)N_EXP * D_OUT * D_H];   // We^T [e][o][k], fp16
__device__ int   g_cnt[32];                             // [0:16] counts, [16:32] cursor
__device__ int   g_sorted[MAXP];

// ---------------- helpers ----------------
__device__ __forceinline__ uint32_t smem_u32(const void* p) {
    uint32_t a;
    asm("{ .reg .u64 t; cvta.to.shared.u64 t, %1; cvt.u32.u64 %0, t; }" : "=r"(a) : "l"(p));
    return a;
}
__device__ __forceinline__ void cp16(uint32_t dst, const void* src) {
    asm volatile("cp.async.cg.shared.global [%0], [%1], 16;" :: "r"(dst), "l"(src));
}
#define CP_COMMIT()  asm volatile("cp.async.commit_group;")
#define CP_WAIT_2()  asm volatile("cp.async.wait_group 2;")

__device__ __forceinline__ void mma16(float* c, const uint32_t* a, const uint32_t* b) {
    asm volatile(
        "mma.sync.aligned.m16n8k16.row.col.f32.f16.f16.f32 "
        "{%0,%1,%2,%3}, {%4,%5,%6,%7}, {%8,%9}, {%0,%1,%2,%3};"
        : "+f"(c[0]), "+f"(c[1]), "+f"(c[2]), "+f"(c[3])
        : "r"(a[0]), "r"(a[1]), "r"(a[2]), "r"(a[3]), "r"(b[0]), "r"(b[1]));
}
__device__ __forceinline__ void ldm_x4(uint32_t* r, uint32_t addr) {
    asm volatile("ldmatrix.sync.aligned.m8n8.x4.shared.b16 {%0,%1,%2,%3}, [%4];"
        : "=r"(r[0]), "=r"(r[1]), "=r"(r[2]), "=r"(r[3]) : "r"(addr));
}

// ---------------- routing ----------------
__global__ void r1_count(const int* __restrict__ num, const int* __restrict__ c) {
    __shared__ int h[N_EXP];
    int tid = threadIdx.x;
    if (tid < N_EXP) h[tid] = 0;
    __syncthreads();
    int i = blockIdx.x * blockDim.x + tid;
    if (i < B_ROWS) atomicAdd(&h[c[num[i]]], 1);
    __syncthreads();
    if (tid < N_EXP && h[tid]) atomicAdd(&g_cnt[tid], h[tid]);
}
__global__ void r3_scatter(const int* __restrict__ num, const int* __restrict__ c) {
    __shared__ int sstart[N_EXP];
    int tid = threadIdx.x;
    if (tid < N_EXP) {                     // inline 16-entry padded scan
        int s = 0;
        for (int e2 = 0; e2 < tid; e2++) s += (g_cnt[e2] + TILE_M - 1) & ~(TILE_M - 1);
        sstart[tid] = s;
    }
    __syncthreads();
    int i = blockIdx.x * blockDim.x + tid;
    if (i >= B_ROWS) return;
    int e = c[num[i]];
    unsigned lane = tid & 31;
    unsigned mask = __match_any_sync(0xffffffffu, e);
    int leader = __ffs(mask) - 1;
    int rank = __popc(mask & ((1u << lane) - 1u));
    int base = 0;
    if ((int)lane == leader) base = atomicAdd(&g_cnt[16 + e], __popc(mask));
    base = __shfl_sync(0xffffffffu, base, leader);
    g_sorted[sstart[e] + base + rank] = i;
}

// ---------------- x -> fp16, original order, row-chunked ----------------
__global__ __launch_bounds__(256) void cvt_x(const float* __restrict__ x, int row0) {
    size_t base = (size_t)row0 * D_IN;
    size_t i = base + ((size_t)blockIdx.x * 256 + threadIdx.x) * 8;
    float4 v0 = *(const float4*)(x + i);
    float4 v1 = *(const float4*)(x + i + 4);
    __half2 h[4];
    h[0] = __floats2half2_rn(v0.x, v0.y);
    h[1] = __floats2half2_rn(v0.z, v0.w);
    h[2] = __floats2half2_rn(v1.x, v1.y);
    h[3] = __floats2half2_rn(v1.z, v1.w);
    *(uint4*)(g_xh + i) = *(uint4*)h;
}

// ---------------- weight transposes (fp16) ----------------
__global__ void tr_w1(const float* __restrict__ W1) {
    __shared__ float t[32][33];
    int x0 = blockIdx.x * 32;   // n
    int y0 = blockIdx.y * 32;   // k
    for (int i = threadIdx.y; i < 32; i += 8)
        t[i][threadIdx.x] = W1[(size_t)(y0 + i) * D_H + x0 + threadIdx.x];
    __syncthreads();
    for (int i = threadIdx.y; i < 32; i += 8)
        g_w1t[(size_t)(x0 + i) * D_IN + y0 + threadIdx.x] = __float2half_rn(t[threadIdx.x][i]);
}
__global__ void tr_we(const float* __restrict__ We) {
    __shared__ float t[32][33];
    int e = blockIdx.z;
    int x0 = blockIdx.x * 32;   // o
    int y0 = blockIdx.y * 32;   // k
    const float* src = We + (size_t)e * D_H * D_OUT;
    for (int i = threadIdx.y; i < 32; i += 8)
        t[i][threadIdx.x] = src[(size_t)(y0 + i) * D_OUT + x0 + threadIdx.x];
    __syncthreads();
    __half* dst = g_wet + (size_t)e * D_OUT * D_H;
    for (int i = threadIdx.y; i < 32; i += 8)
        dst[(size_t)(x0 + i) * D_H + y0 + threadIdx.x] = __float2half_rn(t[threadIdx.x][i]);
}

// ---------------- GEMM1: h = relu(x @ W1 + b1), ORIGINAL order, no routing dep ----------------
__global__ __launch_bounds__(256, 2) void gemm1(const float* __restrict__ b1, int t0) {
    __shared__ float bias_s[128];
    extern __shared__ char dsm[];

    const int tid = threadIdx.x, lane = tid & 31, wid = tid >> 5;
    const int bn = blockIdx.x;
    const int p0 = (blockIdx.y + t0) * TILE_M;

    if (tid < 128) bias_s[tid] = b1[bn * 128 + tid];
    __syncthreads();

    const uint32_t sb = smem_u32(dsm);

    const __half* asrc[2];
    const __half* bsrc[2];
    uint32_t adst[2], bdst[2];
#pragma unroll
    for (int i = 0; i < 2; i++) {
        int id = tid + i * 256;
        int r = id >> 2, q = id & 3;
        asrc[i] = g_xh + (size_t)(p0 + r) * D_IN + q * 8;
        bsrc[i] = g_w1t + (size_t)(bn * 128 + r) * D_IN + q * 8;
        adst[i] = sb + (uint32_t)(r * ROWB + q * 16);
        bdst[i] = adst[i] + STG_B;
    }
#pragma unroll
    for (int s = 0; s < 3; s++) {
        uint32_t off = (uint32_t)(s * STAGE);
        int k = s * 32;
#pragma unroll
        for (int i = 0; i < 2; i++) {
            cp16(adst[i] + off, asrc[i] + k);
            cp16(bdst[i] + off, bsrc[i] + k);
        }
        CP_COMMIT();
    }

    float acc[4][4][4];
#pragma unroll
    for (int mt = 0; mt < 4; mt++)
#pragma unroll
        for (int nt = 0; nt < 4; nt++)
#pragma unroll
            for (int k = 0; k < 4; k++) acc[mt][nt][k] = 0.f;

    const int wm = wid >> 2, wn = wid & 3;
    const int g = lane >> 3, lrow = lane & 7;

    uint32_t aoff[4], boff[2];
#pragma unroll
    for (int mt = 0; mt < 4; mt++)
        aoff[mt] = (uint32_t)((wm * 64 + mt * 16 + (g & 1) * 8 + lrow) * ROWB + (g >> 1) * 16);
#pragma unroll
    for (int p = 0; p < 2; p++)
        boff[p] = (uint32_t)(STG_B + (wn * 32 + p * 16 + (g >> 1) * 8 + lrow) * ROWB + (g & 1) * 16);

    for (int s = 0; s < 16; s++) {
        CP_WAIT_2();
        __syncthreads();
        if (s + 3 < 16) {
            uint32_t off = (uint32_t)(((s + 3) & (NST - 1)) * STAGE);
            int k = (s + 3) * 32;
#pragma unroll
            for (int i = 0; i < 2; i++) {
                cp16(adst[i] + off, asrc[i] + k);
                cp16(bdst[i] + off, bsrc[i] + k);
            }
        }
        CP_COMMIT();

        const uint32_t sbase = sb + (uint32_t)((s & (NST - 1)) * STAGE);
#pragma unroll
        for (int ks = 0; ks < 2; ks++) {
            uint32_t a[4][4], b[2][4];
#pragma unroll
            for (int mt = 0; mt < 4; mt++) ldm_x4(a[mt], sbase + aoff[mt] + ks * 32);
            ldm_x4(b[0], sbase + boff[0] + ks * 32);
            ldm_x4(b[1], sbase + boff[1] + ks * 32);
#pragma unroll
            for (int mt = 0; mt < 4; mt++)
#pragma unroll
                for (int nt = 0; nt < 4; nt++)
                    mma16(acc[mt][nt], a[mt], &b[nt >> 1][(nt & 1) * 2]);
        }
    }

    // epilogue: bias + relu -> g_h fp16 (original order)
    const int lr = lane >> 2, lc = lane & 3;
#pragma unroll
    for (int mt = 0; mt < 4; mt++) {
        int m = wm * 64 + mt * 16 + lr;
#pragma unroll
        for (int nt = 0; nt < 4; nt++) {
            int n = wn * 32 + nt * 8 + lc * 2;
            float bi0 = bias_s[n], bi1 = bias_s[n + 1];
            __half2 v0 = __floats2half2_rn(fmaxf(acc[mt][nt][0] + bi0, 0.f),
                                           fmaxf(acc[mt][nt][1] + bi1, 0.f));
            __half2 v1 = __floats2half2_rn(fmaxf(acc[mt][nt][2] + bi0, 0.f),
                                           fmaxf(acc[mt][nt][3] + bi1, 0.f));
            *(__half2*)(g_h + (size_t)(p0 + m) * D_H + bn * 128 + n) = v0;
            *(__half2*)(g_h + (size_t)(p0 + m + 8) * D_H + bn * 128 + n) = v1;
        }
    }
}

// ---------------- GEMM2: out[orig] = sigmoid(h[sorted-gather] @ We[e]^T + be[e]) ----------------
__global__ __launch_bounds__(256, 2) void gemm2(const float* __restrict__ be,
                                                float* __restrict__ out) {
    __shared__ int   rows_s[128];
    __shared__ float bias_s[128];
    __shared__ int   sstart[N_EXP + 1];
    extern __shared__ char dsm[];

    const int tid = threadIdx.x, lane = tid & 31, wid = tid >> 5;

    if (tid <= N_EXP) {
        int s = 0;
        for (int e2 = 0; e2 < tid; e2++) s += (g_cnt[e2] + TILE_M - 1) & ~(TILE_M - 1);
        sstart[tid] = s;
    }
    __syncthreads();

    const int p0 = blockIdx.x * TILE_M;
    if (p0 >= sstart[N_EXP]) return;

    int e = 0;
    while (e < N_EXP - 1 && sstart[e + 1] <= p0) e++;
    const int valid_end = sstart[e] + g_cnt[e];

    if (tid < 128) {
        int r = g_sorted[p0 + tid];
        rows_s[tid] = min(max(r, 0), B_ROWS - 1);   // clamp padding entries
        bias_s[tid] = be[e * D_OUT + tid];
    }
    __syncthreads();

    const uint32_t sb = smem_u32(dsm);
    const __half* Bb = g_wet + (size_t)e * D_OUT * D_H;

    const __half* asrc[2];
    const __half* bsrc[2];
    uint32_t adst[2], bdst[2];
#pragma unroll
    for (int i = 0; i < 2; i++) {
        int id = tid + i * 256;
        int r = id >> 2, q = id & 3;
        asrc[i] = g_h + (size_t)rows_s[r] * D_H + q * 8;   // gather A rows by sort
        bsrc[i] = Bb + (size_t)r * D_H + q * 8;
        adst[i] = sb + (uint32_t)(r * ROWB + q * 16);
        bdst[i] = adst[i] + STG_B;
    }
#pragma unroll
    for (int s = 0; s < 3; s++) {
        uint32_t off = (uint32_t)(s * STAGE);
        int k = s * 32;
#pragma unroll
        for (int i = 0; i < 2; i++) {
            cp16(adst[i] + off, asrc[i] + k);
            cp16(bdst[i] + off, bsrc[i] + k);
        }
        CP_COMMIT();
    }

    float acc[4][4][4];
#pragma unroll
    for (int mt = 0; mt < 4; mt++)
#pragma unroll
        for (int nt = 0; nt < 4; nt++)
#pragma unroll
            for (int k = 0; k < 4; k++) acc[mt][nt][k] = 0.f;

    const int wm = wid >> 2, wn = wid & 3;
    const int g = lane >> 3, lrow = lane & 7;

    uint32_t aoff[4], boff[2];
#pragma unroll
    for (int mt = 0; mt < 4; mt++)
        aoff[mt] = (uint32_t)((wm * 64 + mt * 16 + (g & 1) * 8 + lrow) * ROWB + (g >> 1) * 16);
#pragma unroll
    for (int p = 0; p < 2; p++)
        boff[p] = (uint32_t)(STG_B + (wn * 32 + p * 16 + (g >> 1) * 8 + lrow) * ROWB + (g & 1) * 16);

    for (int s = 0; s < 16; s++) {
        CP_WAIT_2();
        __syncthreads();
        if (s + 3 < 16) {
            uint32_t off = (uint32_t)(((s + 3) & (NST - 1)) * STAGE);
            int k = (s + 3) * 32;
#pragma unroll
            for (int i = 0; i < 2; i++) {
                cp16(adst[i] + off, asrc[i] + k);
                cp16(bdst[i] + off, bsrc[i] + k);
            }
        }
        CP_COMMIT();

        const uint32_t sbase = sb + (uint32_t)((s & (NST - 1)) * STAGE);
#pragma unroll
        for (int ks = 0; ks < 2; ks++) {
            uint32_t a[4][4], b[2][4];
#pragma unroll
            for (int mt = 0; mt < 4; mt++) ldm_x4(a[mt], sbase + aoff[mt] + ks * 32);
            ldm_x4(b[0], sbase + boff[0] + ks * 32);
            ldm_x4(b[1], sbase + boff[1] + ks * 32);
#pragma unroll
            for (int mt = 0; mt < 4; mt++)
#pragma unroll
                for (int nt = 0; nt < 4; nt++)
                    mma16(acc[mt][nt], a[mt], &b[nt >> 1][(nt & 1) * 2]);
        }
    }

    // epilogue: bias + sigmoid, scatter valid rows
    const int lr = lane >> 2, lc = lane & 3;
#pragma unroll
    for (int mt = 0; mt < 4; mt++) {
        int m = wm * 64 + mt * 16 + lr;
#pragma unroll
        for (int nt = 0; nt < 4; nt++) {
            int n = wn * 32 + nt * 8 + lc * 2;
            float bi0 = bias_s[n], bi1 = bias_s[n + 1];
            if (p0 + m < valid_end) {
                float2 v;
                v.x = 1.f / (1.f + __expf(-(acc[mt][nt][0] + bi0)));
                v.y = 1.f / (1.f + __expf(-(acc[mt][nt][1] + bi1)));
                *(float2*)(out + (size_t)rows_s[m] * D_OUT + n) = v;
            }
            if (p0 + m + 8 < valid_end) {
                float2 v;
                v.x = 1.f / (1.f + __expf(-(acc[mt][nt][2] + bi0)));
                v.y = 1.f / (1.f + __expf(-(acc[mt][nt][3] + bi1)));
                *(float2*)(out + (size_t)rows_s[m + 8] * D_OUT + n) = v;
            }
        }
    }
}

// ---------------- launch: 2-chunk cvt->gemm1 pipeline, routing off critical path ----------------
extern "C" void kernel_launch(void* const* d_in, const int* in_sizes, int n_in,
                              void* d_out, int out_size) {
    const float* x   = (const float*)d_in[0];
    const int*   num = (const int*)d_in[1];
    const int*   c   = (const int*)d_in[2];
    const float* W1  = (const float*)d_in[3];
    const float* b1  = (const float*)d_in[4];
    const float* We  = (const float*)d_in[5];
    const float* be  = (const float*)d_in[6];
    float* out = (float*)d_out;

    static cudaStream_t sC = nullptr, sW = nullptr;
    static cudaEvent_t evFork, evCc[NCHUNK], evW1, evR;
    static void* cnt_ptr = nullptr;
    if (!sC) {
        cudaFuncSetAttribute(gemm1, cudaFuncAttributeMaxDynamicSharedMemorySize, DSMEM);
        cudaFuncSetAttribute(gemm2, cudaFuncAttributeMaxDynamicSharedMemorySize, DSMEM);
        cudaStreamCreateWithFlags(&sC, cudaStreamNonBlocking);
        cudaStreamCreateWithFlags(&sW, cudaStreamNonBlocking);
        cudaEventCreateWithFlags(&evFork, cudaEventDisableTiming);
        for (int i = 0; i < NCHUNK; i++) cudaEventCreateWithFlags(&evCc[i], cudaEventDisableTiming);
        cudaEventCreateWithFlags(&evW1, cudaEventDisableTiming);
        cudaEventCreateWithFlags(&evR,  cudaEventDisableTiming);
        cudaGetSymbolAddress(&cnt_ptr, g_cnt);
    }

    // fork
    cudaEventRecord(evFork, 0);
    cudaStreamWaitEvent(sC, evFork, 0);
    cudaStreamWaitEvent(sW, evFork, 0);

    // sC: x -> fp16 in 2 row-chunks (event after each)
    const int rows_per_chunk = B_ROWS / NCHUNK;               // 32768
    const int blocks_per_chunk = rows_per_chunk * D_IN / (256 * 8);
    for (int i = 0; i < NCHUNK; i++) {
        cvt_x<<<blocks_per_chunk, 256, 0, sC>>>(x, i * rows_per_chunk);
        cudaEventRecord(evCc[i], sC);
    }

    // sW: tr_w1 first (gemm1 dep), then tr_we + routing (gemm2-only deps)
    dim3 tb(32, 8);
    tr_w1<<<dim3(16, 16), tb, 0, sW>>>(W1);
    cudaEventRecord(evW1, sW);
    tr_we<<<dim3(4, 16, 16), tb, 0, sW>>>(We);
    cudaMemsetAsync(cnt_ptr, 0, 32 * sizeof(int), sW);
    r1_count<<<B_ROWS / 256, 256, 0, sW>>>(num, c);
    r3_scatter<<<B_ROWS / 256, 256, 0, sW>>>(num, c);
    cudaEventRecord(evR, sW);

    // main: 2 gemm1 halves pipelined behind cvt chunks
    cudaStreamWaitEvent(0, evW1, 0);
    cudaStreamWaitEvent(0, evCc[0], 0);
    gemm1<<<dim3(4, CH_T), 256, DSMEM>>>(b1, 0);
    cudaStreamWaitEvent(0, evCc[1], 0);
    gemm1<<<dim3(4, CH_T), 256, DSMEM>>>(b1, CH_T);

    // gemm2 after routing + gemm1
    cudaStreamWaitEvent(0, evR, 0);
    gemm2<<<MT1, 256, DSMEM>>>(be, out);
}